// round 2
// baseline (speedup 1.0000x reference)
#include <cuda_runtime.h>
#include <math.h>

// Problem constants
#define Bb   4
#define Hh   4
#define NT   4096
#define BHc  16        // Bb*Hh
#define KVC  240       // per-head KV channels

#define KV_ELEMS  (BHc * NT * KVC)   // 15,728,640
#define CTX_ELEMS (Bb * NT * 960)    // 15,728,640
#define S_ELEMS   (BHc * KVC * KVC)  // 921,600

// Scratch (static device globals; no runtime allocation)
__device__ float g_K[2][KV_ELEMS];     // [modality]
__device__ float g_V[2][KV_ELEMS];     // [modality]
__device__ float g_Q[2][KV_ELEMS];     // [modality], per-scale blocks at QOFF
__device__ float g_P[2][S_ELEMS];      // [output half], scores -> probs in place
__device__ float g_ctx[2][CTX_ELEMS];  // [output half], per-scale blocks at QOFF

// Column gather for the quarter-split of emb_all:
// quarter h = concat over scales of columns [off + h*(c/4), off + (h+1)*(c/4))
__device__ __forceinline__ int kvmap(int h, int c) {
    if (c < 16)  return h * 16 + c;            // scale 0 (c=64),  off 0
    if (c < 48)  return 64  + h * 32  + (c - 16);  // scale 1 (128), off 64
    if (c < 112) return 192 + h * 64  + (c - 48);  // scale 2 (256), off 192
    return 448 + h * 128 + (c - 112);              // scale 3 (512), off 448
}

// ---------------------------------------------------------------------------
// K/V projection: K[bh,n,d] = sum_c kvq[bh,n,c] * wk[d,c]  (and V with wv)
// Tile 64(n) x 48(d), K-chunks of 16. Computes K and V from one A tile.
// ---------------------------------------------------------------------------
__global__ __launch_bounds__(256) void kv_proj_kernel(
    const float* __restrict__ emb, const float* __restrict__ wk,
    const float* __restrict__ wv, int dir)
{
    __shared__ __align__(16) float As[16][68];
    __shared__ float Bk[16][49];
    __shared__ float Bv[16][49];
    int bh = blockIdx.z, b = bh >> 2, h = bh & 3;
    int n0 = blockIdx.x * 64;
    int d0 = blockIdx.y * 48;
    int tid = threadIdx.x;
    int tx = tid & 15, ty = tid >> 4;
    float accK[4][3] = {}, accV[4][3] = {};
    const float* embB = emb + (size_t)b * NT * 960;

    for (int k0 = 0; k0 < KVC; k0 += 16) {
        #pragma unroll
        for (int i = 0; i < 4; i++) {
            int e = tid + 256 * i, kk = e & 15, r = e >> 4;
            As[kk][r] = embB[(size_t)(n0 + r) * 960 + kvmap(h, k0 + kk)];
        }
        #pragma unroll
        for (int i = 0; i < 3; i++) {
            int e = tid + 256 * i, kk = e & 15, d = e >> 4;
            Bk[kk][d] = wk[(d0 + d) * KVC + (k0 + kk)];
            Bv[kk][d] = wv[(d0 + d) * KVC + (k0 + kk)];
        }
        __syncthreads();
        #pragma unroll
        for (int kk = 0; kk < 16; kk++) {
            float4 a4 = *(const float4*)&As[kk][tx * 4];
            float av[4] = {a4.x, a4.y, a4.z, a4.w};
            float bk0 = Bk[kk][ty*3], bk1 = Bk[kk][ty*3+1], bk2 = Bk[kk][ty*3+2];
            float bv0 = Bv[kk][ty*3], bv1 = Bv[kk][ty*3+1], bv2 = Bv[kk][ty*3+2];
            #pragma unroll
            for (int i = 0; i < 4; i++) {
                accK[i][0] += av[i] * bk0; accK[i][1] += av[i] * bk1; accK[i][2] += av[i] * bk2;
                accV[i][0] += av[i] * bv0; accV[i][1] += av[i] * bv1; accV[i][2] += av[i] * bv2;
            }
        }
        __syncthreads();
    }
    float* Ko = g_K[dir];
    float* Vo = g_V[dir];
    #pragma unroll
    for (int i = 0; i < 4; i++) {
        size_t rowoff = ((size_t)bh * NT + n0 + tx * 4 + i) * KVC + d0;
        #pragma unroll
        for (int j = 0; j < 3; j++) {
            Ko[rowoff + ty * 3 + j] = accK[i][j];
            Vo[rowoff + ty * 3 + j] = accV[i][j];
        }
    }
}

// ---------------------------------------------------------------------------
// Q projection: Q[bh,n,d] = sum_c emb[b,n,h*c4+c] * wq[h,d,c]
// Tile 64(n) x 16(d), K-chunks of 16.
// ---------------------------------------------------------------------------
__global__ __launch_bounds__(256) void q_proj_kernel(
    const float* __restrict__ emb, const float* __restrict__ wq,
    int dir, size_t qoff, int c4)
{
    __shared__ __align__(16) float As[16][68];
    __shared__ float Bs[16][17];
    int bh = blockIdx.z, b = bh >> 2, h = bh & 3;
    int n0 = blockIdx.x * 64, d0 = blockIdx.y * 16;
    int cfull = c4 * 4;
    int tid = threadIdx.x, tx = tid & 15, ty = tid >> 4;
    float acc[4] = {};
    const float* embB = emb + (size_t)b * NT * cfull + h * c4;
    const float* w = wq + h * c4 * c4;

    for (int k0 = 0; k0 < c4; k0 += 16) {
        #pragma unroll
        for (int i = 0; i < 4; i++) {
            int e = tid + 256 * i, kk = e & 15, r = e >> 4;
            As[kk][r] = embB[(size_t)(n0 + r) * cfull + k0 + kk];
        }
        {
            int kk = tid & 15, d = tid >> 4;
            Bs[kk][d] = w[(d0 + d) * c4 + k0 + kk];
        }
        __syncthreads();
        #pragma unroll
        for (int kk = 0; kk < 16; kk++) {
            float4 a4 = *(const float4*)&As[kk][tx * 4];
            float bb = Bs[kk][ty];
            acc[0] += a4.x * bb; acc[1] += a4.y * bb;
            acc[2] += a4.z * bb; acc[3] += a4.w * bb;
        }
        __syncthreads();
    }
    float* Q = g_Q[dir] + qoff;
    #pragma unroll
    for (int i = 0; i < 4; i++)
        Q[((size_t)bh * NT + n0 + tx * 4 + i) * c4 + d0 + ty] = acc[i];
}

// ---------------------------------------------------------------------------
// Scores: S[bh,c,k] = (1/sqrt(960)) * sum_n Q[bh,n,c] * K[bh,n,k]
// Output tile 32(c) x 48(k), reduce over n in chunks of 32.
// ---------------------------------------------------------------------------
__global__ __launch_bounds__(256) void scores_kernel(
    int half, size_t qoff, size_t soff, int c4, float scale)
{
    __shared__ float Qs[32][33];
    __shared__ float Ks[32][49];
    int bh = blockIdx.z;
    int cb0 = blockIdx.x * 32, k0 = blockIdx.y * 48;
    int tid = threadIdx.x, tx = tid & 15, ty = tid >> 4;
    float acc[2][3] = {};
    const float* Qbh = g_Q[half] + qoff + (size_t)bh * NT * c4;
    const float* Kbh = g_K[1 - half] + (size_t)bh * NT * KVC;

    for (int n0 = 0; n0 < NT; n0 += 32) {
        #pragma unroll
        for (int i = 0; i < 4; i++) {
            int e = tid + 256 * i, c = e & 31, nn = e >> 5;
            int cg = cb0 + c;
            Qs[nn][c] = (cg < c4) ? Qbh[(size_t)(n0 + nn) * c4 + cg] : 0.f;
        }
        #pragma unroll
        for (int i = 0; i < 6; i++) {
            int e = tid + 256 * i, kk = e % 48, nn = e / 48;
            Ks[nn][kk] = Kbh[(size_t)(n0 + nn) * KVC + k0 + kk];
        }
        __syncthreads();
        #pragma unroll
        for (int nn = 0; nn < 32; nn++) {
            float q0 = Qs[nn][tx * 2], q1 = Qs[nn][tx * 2 + 1];
            float kv0 = Ks[nn][ty * 3], kv1 = Ks[nn][ty * 3 + 1], kv2 = Ks[nn][ty * 3 + 2];
            acc[0][0] += q0 * kv0; acc[0][1] += q0 * kv1; acc[0][2] += q0 * kv2;
            acc[1][0] += q1 * kv0; acc[1][1] += q1 * kv1; acc[1][2] += q1 * kv2;
        }
        __syncthreads();
    }
    float* S = g_P[half] + soff;
    #pragma unroll
    for (int i = 0; i < 2; i++) {
        int c = cb0 + tx * 2 + i;
        if (c < c4) {
            #pragma unroll
            for (int j = 0; j < 3; j++)
                S[((size_t)bh * c4 + c) * KVC + k0 + ty * 3 + j] = acc[i][j] * scale;
        }
    }
}

// ---------------------------------------------------------------------------
// InstanceNorm over (c,k) per (b,h), then row-softmax over k. In place.
// One block per (b,h).
// ---------------------------------------------------------------------------
__global__ __launch_bounds__(256) void norm_softmax_kernel(int half, size_t soff, int c4)
{
    __shared__ float rs[256], rq[256];
    __shared__ float s_mean, s_rinv;
    int tid = threadIdx.x;
    float* Sbh = g_P[half] + soff + (size_t)blockIdx.x * c4 * KVC;
    int M = c4 * KVC;
    float sum = 0.f, sq = 0.f;
    for (int i = tid; i < M; i += 256) { float v = Sbh[i]; sum += v; sq += v * v; }
    rs[tid] = sum; rq[tid] = sq;
    __syncthreads();
    for (int s = 128; s > 0; s >>= 1) {
        if (tid < s) { rs[tid] += rs[tid + s]; rq[tid] += rq[tid + s]; }
        __syncthreads();
    }
    if (tid == 0) {
        float mean = rs[0] / M;
        float var  = rq[0] / M - mean * mean;
        s_mean = mean;
        s_rinv = rsqrtf(var + 1e-5f);
    }
    __syncthreads();
    float mean = s_mean, rinv = s_rinv;
    int warp = tid >> 5, lane = tid & 31;
    for (int c = warp; c < c4; c += 8) {
        float* row = Sbh + (size_t)c * KVC;
        float vals[8];
        float mx = -1e30f;
        #pragma unroll
        for (int t = 0; t < 8; t++) {
            int k = lane + t * 32;
            vals[t] = (k < KVC) ? (row[k] - mean) * rinv : -1e30f;
            mx = fmaxf(mx, vals[t]);
        }
        #pragma unroll
        for (int o = 16; o > 0; o >>= 1) mx = fmaxf(mx, __shfl_xor_sync(0xffffffffu, mx, o));
        float se = 0.f;
        #pragma unroll
        for (int t = 0; t < 8; t++) {
            int k = lane + t * 32;
            float e = (k < KVC) ? __expf(vals[t] - mx) : 0.f;
            vals[t] = e; se += e;
        }
        #pragma unroll
        for (int o = 16; o > 0; o >>= 1) se += __shfl_xor_sync(0xffffffffu, se, o);
        float inv = 1.f / se;
        #pragma unroll
        for (int t = 0; t < 8; t++) {
            int k = lane + t * 32;
            if (k < KVC) row[k] = vals[t] * inv;
        }
    }
}

// ---------------------------------------------------------------------------
// ctx[b,n,h*c4+c] = sum_k P[bh,c,k] * V[bh,n,k]
// Tile 64(n) x 16(c), reduce over k=240 in chunks of 16.
// ---------------------------------------------------------------------------
__global__ __launch_bounds__(256) void ctx_kernel(int half, size_t soff, size_t ctxoff, int c4)
{
    __shared__ __align__(16) float Vs[16][68];
    __shared__ float Ps[16][17];
    int bh = blockIdx.z, b = bh >> 2, h = bh & 3;
    int n0 = blockIdx.x * 64, c0 = blockIdx.y * 16;
    int cfull = c4 * 4;
    int tid = threadIdx.x, tx = tid & 15, ty = tid >> 4;
    float acc[4] = {};
    const float* Vbh = g_V[1 - half] + (size_t)bh * NT * KVC;
    const float* Pbh = g_P[half] + soff + (size_t)bh * c4 * KVC;

    for (int k0 = 0; k0 < KVC; k0 += 16) {
        #pragma unroll
        for (int i = 0; i < 4; i++) {
            int e = tid + 256 * i, kk = e & 15, r = e >> 4;
            Vs[kk][r] = Vbh[(size_t)(n0 + r) * KVC + k0 + kk];
        }
        {
            int kk = tid & 15, c = tid >> 4;
            Ps[kk][c] = Pbh[(size_t)(c0 + c) * KVC + k0 + kk];
        }
        __syncthreads();
        #pragma unroll
        for (int kk = 0; kk < 16; kk++) {
            float4 a4 = *(const float4*)&Vs[kk][tx * 4];
            float bb = Ps[kk][ty];
            acc[0] += a4.x * bb; acc[1] += a4.y * bb;
            acc[2] += a4.z * bb; acc[3] += a4.w * bb;
        }
        __syncthreads();
    }
    float* C = g_ctx[half] + ctxoff;
    #pragma unroll
    for (int i = 0; i < 4; i++)
        C[((size_t)b * NT + n0 + tx * 4 + i) * cfull + h * c4 + c0 + ty] = acc[i];
}

// ---------------------------------------------------------------------------
// Output projection: out[m, outoff+d] = sum_c ctx[m,c] * w[d,c]
// Tile 64(m) x 64(d), 4x4 microtile, K-chunks of 16.
// ---------------------------------------------------------------------------
__global__ __launch_bounds__(256) void out_proj_kernel(
    int half, size_t ctxoff, const float* __restrict__ w,
    float* __restrict__ out, int cfull, int outoff)
{
    __shared__ __align__(16) float As[16][68];
    __shared__ __align__(16) float Bs[16][68];
    int m0 = blockIdx.x * 64, d0 = blockIdx.y * 64;
    int tid = threadIdx.x, tx = tid & 15, ty = tid >> 4;
    float acc[4][4] = {};
    const float* ctx = g_ctx[half] + ctxoff;

    for (int k0 = 0; k0 < cfull; k0 += 16) {
        #pragma unroll
        for (int i = 0; i < 4; i++) {
            int e = tid + 256 * i, kk = e & 15, r = e >> 4;
            As[kk][r] = ctx[(size_t)(m0 + r) * cfull + k0 + kk];
            Bs[kk][r] = w[(size_t)(d0 + r) * cfull + k0 + kk];
        }
        __syncthreads();
        #pragma unroll
        for (int kk = 0; kk < 16; kk++) {
            float4 a4 = *(const float4*)&As[kk][tx * 4];
            float4 b4 = *(const float4*)&Bs[kk][ty * 4];
            float av[4] = {a4.x, a4.y, a4.z, a4.w};
            float bv[4] = {b4.x, b4.y, b4.z, b4.w};
            #pragma unroll
            for (int i = 0; i < 4; i++)
                #pragma unroll
                for (int j = 0; j < 4; j++)
                    acc[i][j] += av[i] * bv[j];
        }
        __syncthreads();
    }
    #pragma unroll
    for (int i = 0; i < 4; i++) {
        size_t rowoff = (size_t)(m0 + tx * 4 + i) * 1920 + outoff;
        #pragma unroll
        for (int j = 0; j < 4; j++)
            out[rowoff + d0 + ty * 4 + j] = acc[i][j];
    }
}

// ---------------------------------------------------------------------------
extern "C" void kernel_launch(void* const* d_in, const int* in_sizes, int n_in,
                              void* d_out, int out_size)
{
    const float *emb[2][4], *emball[2], *wq[2][4], *wkp[2], *wvp[2], *wout[2][4];

    if (in_sizes[1] == 1048576) {
        // setup_inputs() dict order:
        // emb1, embd1, emb2, embd2, emb3, embd3, emb4, embd4, emb_all, emb_alld,
        // (wq,wqd,wout,woutd) x 4 scales, wk, wv, wkd, wvd
        for (int s = 0; s < 4; s++) {
            emb[0][s] = (const float*)d_in[2 * s];
            emb[1][s] = (const float*)d_in[2 * s + 1];
        }
        emball[0] = (const float*)d_in[8];
        emball[1] = (const float*)d_in[9];
        for (int s = 0; s < 4; s++) {
            wq[0][s]   = (const float*)d_in[10 + 4 * s];
            wq[1][s]   = (const float*)d_in[11 + 4 * s];
            wout[0][s] = (const float*)d_in[12 + 4 * s];
            wout[1][s] = (const float*)d_in[13 + 4 * s];
        }
        wkp[0] = (const float*)d_in[26];
        wvp[0] = (const float*)d_in[27];
        wkp[1] = (const float*)d_in[28];
        wvp[1] = (const float*)d_in[29];
    } else {
        // reference() signature order:
        // emb1..4, emb_all, embd1..4, emb_alld, wq1..4, wqd1..4,
        // wk, wv, wkd, wvd, wout1..4, woutd1..4
        for (int s = 0; s < 4; s++) {
            emb[0][s] = (const float*)d_in[s];
            emb[1][s] = (const float*)d_in[5 + s];
        }
        emball[0] = (const float*)d_in[4];
        emball[1] = (const float*)d_in[9];
        for (int s = 0; s < 4; s++) {
            wq[0][s] = (const float*)d_in[10 + s];
            wq[1][s] = (const float*)d_in[14 + s];
        }
        wkp[0] = (const float*)d_in[18];
        wvp[0] = (const float*)d_in[19];
        wkp[1] = (const float*)d_in[20];
        wvp[1] = (const float*)d_in[21];
        for (int s = 0; s < 4; s++) {
            wout[0][s] = (const float*)d_in[22 + s];
            wout[1][s] = (const float*)d_in[26 + s];
        }
    }

    float* out = (float*)d_out;
    static const int    c4s[4]   = {16, 32, 64, 128};
    static const size_t QOFFs[4] = {0, 1048576, 3145728, 7340032}; // BH*NT * prefix(c4)
    static const size_t SOFFs[4] = {0, 61440, 184320, 430080};     // BH*240 * prefix(c4)
    static const int    OBASE[4] = {0, 64, 192, 448};
    const float scale = 1.0f / sqrtf(960.0f);

    // 1) K/V projections (both modalities)
    for (int m = 0; m < 2; m++)
        kv_proj_kernel<<<dim3(NT / 64, 5, BHc), 256>>>(emball[m], wkp[m], wvp[m], m);

    // 2) Q projections
    for (int m = 0; m < 2; m++)
        for (int s = 0; s < 4; s++)
            q_proj_kernel<<<dim3(NT / 64, c4s[s] / 16, BHc), 256>>>(
                emb[m][s], wq[m][s], m, QOFFs[s], c4s[s]);

    // 3) Scores (cross-modal: half o uses Q[o] with K[1-o])
    for (int o = 0; o < 2; o++)
        for (int s = 0; s < 4; s++)
            scores_kernel<<<dim3((c4s[s] + 31) / 32, 5, BHc), 256>>>(
                o, QOFFs[s], SOFFs[s], c4s[s], scale);

    // 4) InstanceNorm + softmax
    for (int o = 0; o < 2; o++)
        for (int s = 0; s < 4; s++)
            norm_softmax_kernel<<<BHc, 256>>>(o, SOFFs[s], c4s[s]);

    // 5) Context (uses V[1-o])
    for (int o = 0; o < 2; o++)
        for (int s = 0; s < 4; s++)
            ctx_kernel<<<dim3(NT / 64, c4s[s] / 16, BHc), 256>>>(
                o, SOFFs[s], QOFFs[s], c4s[s]);

    // 6) Output projections, written directly into the concatenated output
    for (int o = 0; o < 2; o++)
        for (int s = 0; s < 4; s++)
            out_proj_kernel<<<dim3((Bb * NT) / 64, (4 * c4s[s]) / 64, 1), 256>>>(
                o, QOFFs[s], wout[o][s], out, 4 * c4s[s], o * 960 + OBASE[s]);
}

// round 3
// speedup vs baseline: 1.8322x; 1.8322x over previous
#include <cuda_runtime.h>
#include <math.h>

#define NT   4096
#define BHc  16
#define KVC  240

// Scratch (static device globals; no runtime allocation)
__device__ float g_K[2][BHc * NT * KVC];    // [modality][bh][n][240]
__device__ float g_V[2][BHc * NT * KVC];
__device__ float g_Q[2][BHc * NT * KVC];    // [modality][bh][n][240] (scales at QCOL)
__device__ float g_P[2][BHc * KVC * KVC];   // [half][bh][c_all 240][k 240]
__device__ float g_ctx[2][BHc * NT * KVC];  // [half][bh][n][c_all 240]

typedef unsigned long long ull;

#define FMA2(d, a, b) asm("fma.rn.f32x2 %0, %1, %2, %0;" : "+l"(d) : "l"(a), "l"(b))

__device__ __forceinline__ float2 unpack2(ull v) {
    float2 f;
    f.x = __uint_as_float((unsigned)(v & 0xffffffffu));
    f.y = __uint_as_float((unsigned)(v >> 32));
    return f;
}

// quarter-split column map for emb_all; chunk bases are 16-aligned and never
// cross a scale boundary, so kvmap(h, k0+kk) == kvmap(h,k0)+kk within a chunk.
__device__ __forceinline__ int kvmap0(int h, int c) {
    if (c < 16)  return h * 16 + c;
    if (c < 48)  return 64  + h * 32  + (c - 16);
    if (c < 112) return 192 + h * 64  + (c - 48);
    return 448 + h * 128 + (c - 112);
}

// Inner product step: 16 k-slices, 8(rows, as 4 f32x2 pairs) x 5(cols) microtile.
#define COMPUTE16()                                                         \
    _Pragma("unroll")                                                       \
    for (int kk = 0; kk < 16; kk++) {                                       \
        ulonglong2 A0 = *(const ulonglong2*)&As[kk][ty * 8];                \
        ulonglong2 A1 = *(const ulonglong2*)&As[kk][ty * 8 + 4];            \
        ull a0 = A0.x, a1 = A0.y, a2 = A1.x, a3 = A1.y;                     \
        _Pragma("unroll")                                                   \
        for (int j = 0; j < 5; j++) {                                       \
            ull bv = *(const ull*)&Bs[kk][tx * 10 + 2 * j];                 \
            FMA2(acc[0][j], a0, bv);                                        \
            FMA2(acc[1][j], a1, bv);                                        \
            FMA2(acc[2][j], a2, bv);                                        \
            FMA2(acc[3][j], a3, bv);                                        \
        }                                                                   \
    }

// ---------------------------------------------------------------------------
// K/V projection: [bh][n][240] K and V. Tile 128(n) x 80(d), reduce c=240.
// blockIdx.y: 0..2 -> K d-block, 3..5 -> V d-block (shared A tile per launch).
// ---------------------------------------------------------------------------
__global__ __launch_bounds__(256) void gemm_kv(
    const float* __restrict__ emb, const float* __restrict__ wk,
    const float* __restrict__ wv, int dir)
{
    __shared__ __align__(16) float As[16][132];
    __shared__ __align__(16) float Bs[16][170];
    const int tid = threadIdx.x, tx = tid & 15, ty = tid >> 4;
    const int bh = blockIdx.z, b = bh >> 2, h = bh & 3;
    const int n0 = blockIdx.x * 128;
    const int yb = blockIdx.y;
    const float* w = (yb < 3) ? wk : wv;
    const int d0 = (yb < 3 ? yb : yb - 3) * 80;
    float* outp = (yb < 3) ? g_K[dir] : g_V[dir];
    const float* embB = emb + (size_t)b * NT * 960;

    ull acc[4][5] = {};
    float ra[8], rb[5];
    {
        int base = kvmap0(h, 0);
        #pragma unroll
        for (int i = 0; i < 8; i++) { int e = tid + 256 * i;
            ra[i] = embB[(size_t)(n0 + (e >> 4)) * 960 + base + (e & 15)]; }
        #pragma unroll
        for (int i = 0; i < 5; i++) { int e = tid + 256 * i;
            rb[i] = w[(d0 + (e >> 4)) * KVC + (e & 15)]; }
    }
    for (int k0 = 0; k0 < KVC; k0 += 16) {
        #pragma unroll
        for (int i = 0; i < 8; i++) { int e = tid + 256 * i; As[e & 15][e >> 4] = ra[i]; }
        #pragma unroll
        for (int i = 0; i < 5; i++) { int e = tid + 256 * i;
            *(float2*)&Bs[e & 15][2 * (e >> 4)] = make_float2(rb[i], rb[i]); }
        __syncthreads();
        if (k0 + 16 < KVC) {
            int kn = k0 + 16, base = kvmap0(h, kn);
            #pragma unroll
            for (int i = 0; i < 8; i++) { int e = tid + 256 * i;
                ra[i] = embB[(size_t)(n0 + (e >> 4)) * 960 + base + (e & 15)]; }
            #pragma unroll
            for (int i = 0; i < 5; i++) { int e = tid + 256 * i;
                rb[i] = w[(d0 + (e >> 4)) * KVC + kn + (e & 15)]; }
        }
        COMPUTE16();
        __syncthreads();
    }
    #pragma unroll
    for (int i = 0; i < 4; i++) {
        size_t o0 = ((size_t)bh * NT + n0 + ty * 8 + 2 * i) * KVC + d0 + tx * 5;
        #pragma unroll
        for (int j = 0; j < 5; j++) {
            float2 v = unpack2(acc[i][j]);
            outp[o0 + j] = v.x;
            outp[o0 + KVC + j] = v.y;
        }
    }
}

// ---------------------------------------------------------------------------
// Q projection into g_Q[mod][bh][n][QCOL[s] + d]. Tile 128(n) x 80(d), reduce c4.
// ---------------------------------------------------------------------------
__global__ __launch_bounds__(256) void gemm_q(
    const float* __restrict__ emb, const float* __restrict__ wq,
    int mod, int qcol, int c4)
{
    __shared__ __align__(16) float As[16][132];
    __shared__ __align__(16) float Bs[16][170];
    const int tid = threadIdx.x, tx = tid & 15, ty = tid >> 4;
    const int bh = blockIdx.z, b = bh >> 2, h = bh & 3;
    const int n0 = blockIdx.x * 128;
    const int d0 = blockIdx.y * 80;
    const int cfull = c4 * 4;
    const float* embB = emb + (size_t)b * NT * cfull + h * c4;
    const float* w = wq + h * c4 * c4;

    ull acc[4][5] = {};
    float ra[8], rb[5];
    #pragma unroll
    for (int i = 0; i < 8; i++) { int e = tid + 256 * i;
        ra[i] = embB[(size_t)(n0 + (e >> 4)) * cfull + (e & 15)]; }
    #pragma unroll
    for (int i = 0; i < 5; i++) { int e = tid + 256 * i; int j = d0 + (e >> 4);
        rb[i] = (j < c4) ? w[j * c4 + (e & 15)] : 0.f; }

    for (int k0 = 0; k0 < c4; k0 += 16) {
        #pragma unroll
        for (int i = 0; i < 8; i++) { int e = tid + 256 * i; As[e & 15][e >> 4] = ra[i]; }
        #pragma unroll
        for (int i = 0; i < 5; i++) { int e = tid + 256 * i;
            *(float2*)&Bs[e & 15][2 * (e >> 4)] = make_float2(rb[i], rb[i]); }
        __syncthreads();
        if (k0 + 16 < c4) {
            int kn = k0 + 16;
            #pragma unroll
            for (int i = 0; i < 8; i++) { int e = tid + 256 * i;
                ra[i] = embB[(size_t)(n0 + (e >> 4)) * cfull + kn + (e & 15)]; }
            #pragma unroll
            for (int i = 0; i < 5; i++) { int e = tid + 256 * i; int j = d0 + (e >> 4);
                rb[i] = (j < c4) ? w[j * c4 + kn + (e & 15)] : 0.f; }
        }
        COMPUTE16();
        __syncthreads();
    }
    float* Q = g_Q[mod];
    #pragma unroll
    for (int i = 0; i < 4; i++) {
        size_t o0 = ((size_t)bh * NT + n0 + ty * 8 + 2 * i) * KVC + qcol + d0 + tx * 5;
        #pragma unroll
        for (int j = 0; j < 5; j++) {
            if (d0 + tx * 5 + j < c4) {
                float2 v = unpack2(acc[i][j]);
                Q[o0 + j] = v.x;
                Q[o0 + KVC + j] = v.y;
            }
        }
    }
}

// ---------------------------------------------------------------------------
// Scores: S[half][bh][c_all][k] = scale * sum_n Q[half][bh][n][c] * K[1-half][bh][n][k]
// Tile 128(c) x 80(k), reduce n=4096. grid (2, 3, 32): z = half*16 + bh.
// ---------------------------------------------------------------------------
__global__ __launch_bounds__(256) void gemm_scores(float scale)
{
    __shared__ __align__(16) float As[16][132];
    __shared__ __align__(16) float Bs[16][170];
    const int tid = threadIdx.x, tx = tid & 15, ty = tid >> 4;
    const int half = blockIdx.z >> 4, bh = blockIdx.z & 15;
    const int r0 = blockIdx.x * 128;        // c rows
    const int kc = blockIdx.y * 80;         // k cols
    const float* Q = g_Q[half] + (size_t)bh * NT * KVC;
    const float* K = g_K[1 - half] + (size_t)bh * NT * KVC;

    ull acc[4][5] = {};
    float ra[8], rb[5];
    #pragma unroll
    for (int i = 0; i < 8; i++) { int e = tid + 256 * i; int m = e & 127, nn = e >> 7;
        int cg = r0 + m;
        ra[i] = (cg < KVC) ? Q[(size_t)nn * KVC + cg] : 0.f; }
    #pragma unroll
    for (int i = 0; i < 5; i++) { int e = tid + 256 * i;
        rb[i] = K[(size_t)(e / 80) * KVC + kc + (e % 80)]; }

    for (int n0 = 0; n0 < NT; n0 += 16) {
        #pragma unroll
        for (int i = 0; i < 8; i++) { int e = tid + 256 * i; As[e >> 7][e & 127] = ra[i]; }
        #pragma unroll
        for (int i = 0; i < 5; i++) { int e = tid + 256 * i;
            *(float2*)&Bs[e / 80][2 * (e % 80)] = make_float2(rb[i], rb[i]); }
        __syncthreads();
        if (n0 + 16 < NT) {
            int nn0 = n0 + 16;
            #pragma unroll
            for (int i = 0; i < 8; i++) { int e = tid + 256 * i; int m = e & 127;
                int cg = r0 + m;
                ra[i] = (cg < KVC) ? Q[(size_t)(nn0 + (e >> 7)) * KVC + cg] : 0.f; }
            #pragma unroll
            for (int i = 0; i < 5; i++) { int e = tid + 256 * i;
                rb[i] = K[(size_t)(nn0 + e / 80) * KVC + kc + (e % 80)]; }
        }
        COMPUTE16();
        __syncthreads();
    }
    float* S = g_P[half] + (size_t)bh * KVC * KVC;
    #pragma unroll
    for (int i = 0; i < 4; i++) {
        int r = r0 + ty * 8 + 2 * i;
        #pragma unroll
        for (int j = 0; j < 5; j++) {
            float2 v = unpack2(acc[i][j]);
            if (r < KVC)     S[(size_t)r * KVC + kc + tx * 5 + j] = v.x * scale;
            if (r + 1 < KVC) S[(size_t)(r + 1) * KVC + kc + tx * 5 + j] = v.y * scale;
        }
    }
}

// ---------------------------------------------------------------------------
// InstanceNorm over the scale's (c4 x 240) block per (half,bh), then row softmax.
// ---------------------------------------------------------------------------
__global__ __launch_bounds__(256) void norm_softmax_kernel(int half, int qcol, int c4)
{
    __shared__ float rs[256], rq[256];
    __shared__ float s_mean, s_rinv;
    int tid = threadIdx.x;
    float* Sbh = g_P[half] + (size_t)blockIdx.x * KVC * KVC + (size_t)qcol * KVC;
    int M = c4 * KVC;
    float sum = 0.f, sq = 0.f;
    for (int i = tid; i < M; i += 256) { float v = Sbh[i]; sum += v; sq += v * v; }
    rs[tid] = sum; rq[tid] = sq;
    __syncthreads();
    for (int s = 128; s > 0; s >>= 1) {
        if (tid < s) { rs[tid] += rs[tid + s]; rq[tid] += rq[tid + s]; }
        __syncthreads();
    }
    if (tid == 0) {
        float mean = rs[0] / M;
        float var  = rq[0] / M - mean * mean;
        s_mean = mean;
        s_rinv = rsqrtf(var + 1e-5f);
    }
    __syncthreads();
    float mean = s_mean, rinv = s_rinv;
    int warp = tid >> 5, lane = tid & 31;
    for (int c = warp; c < c4; c += 8) {
        float* row = Sbh + (size_t)c * KVC;
        float vals[8];
        float mx = -1e30f;
        #pragma unroll
        for (int t = 0; t < 8; t++) {
            int k = lane + t * 32;
            vals[t] = (k < KVC) ? (row[k] - mean) * rinv : -1e30f;
            mx = fmaxf(mx, vals[t]);
        }
        #pragma unroll
        for (int o = 16; o > 0; o >>= 1) mx = fmaxf(mx, __shfl_xor_sync(0xffffffffu, mx, o));
        float se = 0.f;
        #pragma unroll
        for (int t = 0; t < 8; t++) {
            int k = lane + t * 32;
            float e = (k < KVC) ? __expf(vals[t] - mx) : 0.f;
            vals[t] = e; se += e;
        }
        #pragma unroll
        for (int o = 16; o > 0; o >>= 1) se += __shfl_xor_sync(0xffffffffu, se, o);
        float inv = 1.f / se;
        #pragma unroll
        for (int t = 0; t < 8; t++) {
            int k = lane + t * 32;
            if (k < KVC) row[k] = vals[t] * inv;
        }
    }
}

// ---------------------------------------------------------------------------
// Context: ctx[half][bh][n][c_all] = sum_k V[1-half][bh][n][k] * P[half][bh][c][k]
// Tile 128(n) x 80(c), reduce k=240. grid (32, 3, 32).
// ---------------------------------------------------------------------------
__global__ __launch_bounds__(256) void gemm_ctx()
{
    __shared__ __align__(16) float As[16][132];
    __shared__ __align__(16) float Bs[16][170];
    const int tid = threadIdx.x, tx = tid & 15, ty = tid >> 4;
    const int half = blockIdx.z >> 4, bh = blockIdx.z & 15;
    const int n0 = blockIdx.x * 128;
    const int c0 = blockIdx.y * 80;
    const float* V = g_V[1 - half] + (size_t)bh * NT * KVC;
    const float* P = g_P[half] + (size_t)bh * KVC * KVC;

    ull acc[4][5] = {};
    float ra[8], rb[5];
    #pragma unroll
    for (int i = 0; i < 8; i++) { int e = tid + 256 * i;
        ra[i] = V[(size_t)(n0 + (e >> 4)) * KVC + (e & 15)]; }
    #pragma unroll
    for (int i = 0; i < 5; i++) { int e = tid + 256 * i;
        rb[i] = P[(size_t)(c0 + (e >> 4)) * KVC + (e & 15)]; }

    for (int k0 = 0; k0 < KVC; k0 += 16) {
        #pragma unroll
        for (int i = 0; i < 8; i++) { int e = tid + 256 * i; As[e & 15][e >> 4] = ra[i]; }
        #pragma unroll
        for (int i = 0; i < 5; i++) { int e = tid + 256 * i;
            *(float2*)&Bs[e & 15][2 * (e >> 4)] = make_float2(rb[i], rb[i]); }
        __syncthreads();
        if (k0 + 16 < KVC) {
            int kn = k0 + 16;
            #pragma unroll
            for (int i = 0; i < 8; i++) { int e = tid + 256 * i;
                ra[i] = V[(size_t)(n0 + (e >> 4)) * KVC + kn + (e & 15)]; }
            #pragma unroll
            for (int i = 0; i < 5; i++) { int e = tid + 256 * i;
                rb[i] = P[(size_t)(c0 + (e >> 4)) * KVC + kn + (e & 15)]; }
        }
        COMPUTE16();
        __syncthreads();
    }
    float* C = g_ctx[half];
    #pragma unroll
    for (int i = 0; i < 4; i++) {
        size_t o0 = ((size_t)bh * NT + n0 + ty * 8 + 2 * i) * KVC + c0 + tx * 5;
        #pragma unroll
        for (int j = 0; j < 5; j++) {
            float2 v = unpack2(acc[i][j]);
            C[o0 + j] = v.x;
            C[o0 + KVC + j] = v.y;
        }
    }
}

// ---------------------------------------------------------------------------
// Output projection: out[m][half*960 + obase + d] = sum_c ctxGathered[m][c] * w[d][c]
// Tile 128(m) x 80(d), reduce cfull = 4*c4. grid (128, yt, 2): z = half.
// ---------------------------------------------------------------------------
__global__ __launch_bounds__(256) void gemm_out(
    int qcol, int c4, const float* __restrict__ w0, const float* __restrict__ w1,
    float* __restrict__ out, int obase)
{
    __shared__ __align__(16) float As[16][132];
    __shared__ __align__(16) float Bs[16][170];
    const int tid = threadIdx.x, tx = tid & 15, ty = tid >> 4;
    const int half = blockIdx.z;
    const float* w = half ? w1 : w0;
    const int m0 = blockIdx.x * 128;
    const int d0 = blockIdx.y * 80;
    const int cfull = c4 * 4;
    const float* ctx = g_ctx[half];
    const int ooff = half * 960 + obase;

    ull acc[4][5] = {};
    float ra[8], rb[5];
    {
        int hh = 0, loc0 = 0;
        #pragma unroll
        for (int i = 0; i < 8; i++) { int e = tid + 256 * i; int mg = m0 + (e >> 4);
            int b = mg >> 12, n = mg & 4095;
            ra[i] = ctx[((size_t)(b * 4 + hh) * NT + n) * KVC + qcol + loc0 + (e & 15)]; }
        #pragma unroll
        for (int i = 0; i < 5; i++) { int e = tid + 256 * i; int j = d0 + (e >> 4);
            rb[i] = (j < cfull) ? w[(size_t)j * cfull + (e & 15)] : 0.f; }
    }
    for (int k0 = 0; k0 < cfull; k0 += 16) {
        #pragma unroll
        for (int i = 0; i < 8; i++) { int e = tid + 256 * i; As[e & 15][e >> 4] = ra[i]; }
        #pragma unroll
        for (int i = 0; i < 5; i++) { int e = tid + 256 * i;
            *(float2*)&Bs[e & 15][2 * (e >> 4)] = make_float2(rb[i], rb[i]); }
        __syncthreads();
        if (k0 + 16 < cfull) {
            int kn = k0 + 16;
            int hh = kn / c4, loc0 = kn - hh * c4;
            #pragma unroll
            for (int i = 0; i < 8; i++) { int e = tid + 256 * i; int mg = m0 + (e >> 4);
                int b = mg >> 12, n = mg & 4095;
                ra[i] = ctx[((size_t)(b * 4 + hh) * NT + n) * KVC + qcol + loc0 + (e & 15)]; }
            #pragma unroll
            for (int i = 0; i < 5; i++) { int e = tid + 256 * i; int j = d0 + (e >> 4);
                rb[i] = (j < cfull) ? w[(size_t)j * cfull + kn + (e & 15)] : 0.f; }
        }
        COMPUTE16();
        __syncthreads();
    }
    #pragma unroll
    for (int i = 0; i < 4; i++) {
        size_t o0 = (size_t)(m0 + ty * 8 + 2 * i) * 1920 + ooff + d0 + tx * 5;
        #pragma unroll
        for (int j = 0; j < 5; j++) {
            if (d0 + tx * 5 + j < cfull) {
                float2 v = unpack2(acc[i][j]);
                out[o0 + j] = v.x;
                out[o0 + 1920 + j] = v.y;
            }
        }
    }
}

// ---------------------------------------------------------------------------
extern "C" void kernel_launch(void* const* d_in, const int* in_sizes, int n_in,
                              void* d_out, int out_size)
{
    const float *emb[2][4], *emball[2], *wq[2][4], *wkp[2], *wvp[2], *wout[2][4];

    if (in_sizes[1] == 1048576) {
        // dict order
        for (int s = 0; s < 4; s++) {
            emb[0][s] = (const float*)d_in[2 * s];
            emb[1][s] = (const float*)d_in[2 * s + 1];
        }
        emball[0] = (const float*)d_in[8];
        emball[1] = (const float*)d_in[9];
        for (int s = 0; s < 4; s++) {
            wq[0][s]   = (const float*)d_in[10 + 4 * s];
            wq[1][s]   = (const float*)d_in[11 + 4 * s];
            wout[0][s] = (const float*)d_in[12 + 4 * s];
            wout[1][s] = (const float*)d_in[13 + 4 * s];
        }
        wkp[0] = (const float*)d_in[26];
        wvp[0] = (const float*)d_in[27];
        wkp[1] = (const float*)d_in[28];
        wvp[1] = (const float*)d_in[29];
    } else {
        // signature order
        for (int s = 0; s < 4; s++) {
            emb[0][s] = (const float*)d_in[s];
            emb[1][s] = (const float*)d_in[5 + s];
        }
        emball[0] = (const float*)d_in[4];
        emball[1] = (const float*)d_in[9];
        for (int s = 0; s < 4; s++) {
            wq[0][s] = (const float*)d_in[10 + s];
            wq[1][s] = (const float*)d_in[14 + s];
        }
        wkp[0] = (const float*)d_in[18];
        wvp[0] = (const float*)d_in[19];
        wkp[1] = (const float*)d_in[20];
        wvp[1] = (const float*)d_in[21];
        for (int s = 0; s < 4; s++) {
            wout[0][s] = (const float*)d_in[22 + s];
            wout[1][s] = (const float*)d_in[26 + s];
        }
    }

    float* out = (float*)d_out;
    static const int c4s[4]  = {16, 32, 64, 128};
    static const int QCOL[4] = {0, 16, 48, 112};
    static const int OBASE[4] = {0, 64, 192, 448};
    static const int YT[4]   = {1, 2, 4, 7};     // ceil(4*c4/80)
    const float scale = 1.0f / sqrtf(960.0f);

    // 1) K/V projections
    for (int m = 0; m < 2; m++)
        gemm_kv<<<dim3(32, 6, BHc), 256>>>(emball[m], wkp[m], wvp[m], m);

    // 2) Q projections (concatenated layout)
    for (int m = 0; m < 2; m++)
        for (int s = 0; s < 4; s++)
            gemm_q<<<dim3(32, (c4s[s] + 79) / 80, BHc), 256>>>(
                emb[m][s], wq[m][s], m, QCOL[s], c4s[s]);

    // 3) Scores: one launch covers both halves and all scales
    gemm_scores<<<dim3(2, 3, 32), 256>>>(scale);

    // 4) InstanceNorm + softmax per (half, scale)
    for (int o = 0; o < 2; o++)
        for (int s = 0; s < 4; s++)
            norm_softmax_kernel<<<BHc, 256>>>(o, QCOL[s], c4s[s]);

    // 5) Context: one launch
    gemm_ctx<<<dim3(32, 3, 32), 256>>>();

    // 6) Output projections (both halves per launch)
    for (int s = 0; s < 4; s++)
        gemm_out<<<dim3(128, YT[s], 2), 256>>>(
            QCOL[s], c4s[s], wout[0][s], wout[1][s], out, OBASE[s]);
}